// round 6
// baseline (speedup 1.0000x reference)
#include <cuda_runtime.h>
#include <cuda_bf16.h>

#define N      512
#define DIM    256
#define EPSV   1e-12f
#define KLOG2E 14.4269504088896340736f   // SCAL * log2(e)

#define NBLK   128        // 4 anchors per block
#define KC     16         // k-chunk
#define NKC    (DIM / KC) // 16 chunks
#define BPITCH 513        // k-major B pitch (odd -> conflict-free column reads)

__device__ float    g_partial[NBLK];
__device__ float    g_pcount[NBLK];
__device__ unsigned g_done = 0;

__device__ __forceinline__ float ex2a(float x) {
    float y; asm("ex2.approx.ftz.f32 %0, %1;" : "=f"(y) : "f"(x)); return y;
}
__device__ __forceinline__ float rcpa(float x) {
    float y; asm("rcp.approx.ftz.f32 %0, %1;" : "=f"(y) : "f"(x)); return y;
}

// ---------------------------------------------------------------------------
// One kernel, 128 independent blocks. Block b owns anchors 4b..4b+3:
//   GEMM row-stripe (4 x 512 x 256) with feat streamed through smem,
//   distances kept in smem, triplet sums, then done-counter final reduce.
// ---------------------------------------------------------------------------
__global__ void __launch_bounds__(256)
k_all(const float* __restrict__ feat, const int* __restrict__ y,
      float* __restrict__ out) {
    __shared__ float As[4][DIM];               // 4 KB, anchor rows
    __shared__ float sqa[4];
    __shared__ int   ysh[N];                   // 2 KB
    __shared__ float pool[KC * BPITCH];        // 32.8 KB: Bst, then phase-2 data
    __shared__ float wsum[8];
    __shared__ int   npos_s[4], nneg_s[4], last_s;

    float* const Bst  = pool;                  // [KC][BPITCH] during GEMM
    float* const xsh  = pool;                  // [4][512] after GEMM
    float* const posR = pool + 4 * N;          // [4][132]
    float* const red  = pool + 4 * N + 4 * 132;// [128]

    const int tid  = threadIdx.x;
    const int bid  = blockIdx.x;
    const int warp = tid >> 5;
    const int lane = tid & 31;
    const int abase = bid * 4;

    const float4* f4 = reinterpret_cast<const float4*>(feat);  // row pitch 64 f4

    // ---- load anchor rows + labels ----
    {
        const int q = tid >> 6, c = tid & 63;       // 4 rows x 64 f4
        float4 v = __ldg(&f4[(abase + q) * 64 + c]);
        *reinterpret_cast<float4*>(&As[q][c * 4]) = v;
    }
    ysh[tid]       = y[tid];
    ysh[tid + 256] = y[tid + 256];
    __syncthreads();

    if (warp < 4) {     // anchor squared norms
        float s = 0.f;
        #pragma unroll
        for (int u = lane; u < DIM; u += 32) { float v = As[warp][u]; s += v * v; }
        #pragma unroll
        for (int o = 16; o > 0; o >>= 1) s += __shfl_xor_sync(0xffffffffu, s, o);
        if (lane == 0) sqa[warp] = s;
    }

    // ---- GEMM: acc[q][0] = dot(anchor q, col tid); acc[q][1] = col tid+256 ----
    float acc00 = 0.f, acc01 = 0.f, acc10 = 0.f, acc11 = 0.f;
    float acc20 = 0.f, acc21 = 0.f, acc30 = 0.f, acc31 = 0.f;
    float sq0 = 0.f, sq1 = 0.f;
    float4 rb[8];

    // prologue: chunk 0 into registers
    #pragma unroll
    for (int s = 0; s < 8; ++s) {
        const int v = tid + s * 256;
        rb[s] = __ldg(&f4[(v >> 2) * 64 + (v & 3)]);
    }

    for (int kc = 0; kc < NKC; ++kc) {
        __syncthreads();
        #pragma unroll
        for (int s = 0; s < 8; ++s) {          // transpose-store chunk
            const int v = tid + s * 256;
            const int j = v >> 2, q4 = v & 3;
            const float4 b = rb[s];
            Bst[(q4 * 4 + 0) * BPITCH + j] = b.x;
            Bst[(q4 * 4 + 1) * BPITCH + j] = b.y;
            Bst[(q4 * 4 + 2) * BPITCH + j] = b.z;
            Bst[(q4 * 4 + 3) * BPITCH + j] = b.w;
        }
        __syncthreads();
        if (kc + 1 < NKC) {                    // prefetch next chunk
            #pragma unroll
            for (int s = 0; s < 8; ++s) {
                const int v = tid + s * 256;
                rb[s] = __ldg(&f4[(v >> 2) * 64 + (kc + 1) * 4 + (v & 3)]);
            }
        }
        #pragma unroll
        for (int k = 0; k < KC; ++k) {
            const float b0 = Bst[k * BPITCH + tid];
            const float b1 = Bst[k * BPITCH + tid + 256];
            const int kg = kc * KC + k;
            const float a0 = As[0][kg], a1 = As[1][kg];
            const float a2 = As[2][kg], a3 = As[3][kg];
            acc00 += a0 * b0; acc01 += a0 * b1;
            acc10 += a1 * b0; acc11 += a1 * b1;
            acc20 += a2 * b0; acc21 += a2 * b1;
            acc30 += a3 * b0; acc31 += a3 * b1;
            sq0 += b0 * b0;   sq1 += b1 * b1;
        }
    }
    __syncthreads();   // Bst reads done; pool becomes xsh

    // ---- epilogue: x = K*log2e * D, into smem ----
    {
        float a0[4] = {acc00, acc10, acc20, acc30};
        float a1[4] = {acc01, acc11, acc21, acc31};
        #pragma unroll
        for (int q = 0; q < 4; ++q) {
            const float d0 = sqrtf(fmaxf(sqa[q] + sq0 - 2.f * a0[q], EPSV));
            const float d1 = sqrtf(fmaxf(sqa[q] + sq1 - 2.f * a1[q], EPSV));
            xsh[q * N + tid]       = d0 * KLOG2E;
            xsh[q * N + tid + 256] = d1 * KLOG2E;
        }
    }
    __syncthreads();

    // ---- positive lists: warp q handles anchor abase+q ----
    if (warp < 4) {
        const int   a  = abase + warp;
        const int   ya = ysh[a];
        const float c  = xsh[warp * N + ((a + 1) & (N - 1))];
        int cnt = 0, same = 0;
        for (int base = 0; base < N; base += 32) {
            const int  j  = base + lane;
            const bool sc = (ysh[j] == ya);
            const bool v  = sc && (j != a);
            const unsigned mv = __ballot_sync(0xffffffffu, v);
            if (v) {
                const int slot = cnt + __popc(mv & ((1u << lane) - 1u));
                float rp = ex2a(c - xsh[warp * N + j]);
                posR[warp * 132 + slot] = fminf(fmaxf(rp, 1e-30f), 1e30f);
            }
            cnt  += __popc(mv);
            same += __popc(__ballot_sync(0xffffffffu, sc));
        }
        if (lane == 0) { npos_s[warp] = cnt; nneg_s[warp] = N - same; }
    }
    __syncthreads();

    // ---- sigmoid sums: thread owns negatives tid and tid+256 ----
    const float INF = __int_as_float(0x7f800000);
    const int   yn0 = ysh[tid];
    const int   yn1 = ysh[tid + 256];

    float accT = 0.f;
    #pragma unroll
    for (int q = 0; q < 4; ++q) {
        const int   a  = abase + q;
        const int   ya = ysh[a];
        const float c  = xsh[q * N + ((a + 1) & (N - 1))];
        const float e0 = (yn0 != ya) ? ex2a(xsh[q * N + tid]       - c) : INF;
        const float e1 = (yn1 != ya) ? ex2a(xsh[q * N + tid + 256] - c) : INF;
        const int npos = npos_s[q];
        for (int p = 0; p < npos; ++p) {
            const float rp = posR[q * 132 + p];
            accT += rcpa(fmaf(e0, rp, 1.f));
            accT += rcpa(fmaf(e1, rp, 1.f));
        }
    }

    #pragma unroll
    for (int o = 16; o > 0; o >>= 1) accT += __shfl_xor_sync(0xffffffffu, accT, o);
    if (lane == 0) wsum[warp] = accT;
    __syncthreads();

    if (tid == 0) {
        float s = 0.f;
        #pragma unroll
        for (int w = 0; w < 8; ++w) s += wsum[w];
        float cc = 0.f;
        #pragma unroll
        for (int q = 0; q < 4; ++q) cc += (float)(npos_s[q] * nneg_s[q]);
        g_partial[bid] = s;
        g_pcount[bid]  = cc;
        __threadfence();
        const unsigned t = atomicAdd(&g_done, 1u);
        last_s = (t == NBLK - 1);
    }
    __syncthreads();

    // ---- final reduce (last block) ----
    if (last_s) {
        __threadfence();
        if (tid < NBLK) red[tid] = __ldcg(&g_partial[tid]);
        __syncthreads();
        #pragma unroll
        for (int st = 64; st > 0; st >>= 1) {
            if (tid < st) red[tid] += red[tid + st];
            __syncthreads();
        }
        const float tot = red[0];
        __syncthreads();
        if (tid < NBLK) red[tid] = __ldcg(&g_pcount[tid]);
        __syncthreads();
        #pragma unroll
        for (int st = 64; st > 0; st >>= 1) {
            if (tid < st) red[tid] += red[tid + st];
            __syncthreads();
        }
        if (tid == 0) {
            out[0] = tot / red[0];
            g_done = 0;                  // reset for next graph replay
        }
    }
}

// ---------------------------------------------------------------------------
extern "C" void kernel_launch(void* const* d_in, const int* in_sizes, int n_in,
                              void* d_out, int out_size) {
    const float* feat = (const float*)d_in[0];
    // d_in[1] = logits (unused by the loss)
    const int*   y    = (const int*)d_in[2];
    float*       out  = (float*)d_out;

    k_all<<<NBLK, 256>>>(feat, y, out);
}